// round 2
// baseline (speedup 1.0000x reference)
#include <cuda_runtime.h>
#include <math.h>

#define BATCH   512
#define IN_DIM  768
#define HID     256
#define NGEN    4095
#define NOBS    15
#define OUT_DIM 512
#define DIM     64

#define SSTEPS  32
#define TDEG    10

// -------- scratch (static device globals; no runtime allocation) --------
__device__ float g_h[BATCH * HID];        // hidden of enc MLP
__device__ float g_theta[BATCH * NGEN];   // SU(64) angles
__device__ float g_q[BATCH * NOBS];       // expectation values

__device__ const int PAIR_A[15] = {0,0,0,0,0,1,1,1,1,2,2,2,3,3,4};
__device__ const int PAIR_B[15] = {1,2,3,4,5,2,3,4,5,3,4,5,4,5,5};

// ---------------- Kernel A: h = silu(x @ W1 + b1), 8 rows/block ----------------
__global__ void k_mlp1(const float* __restrict__ x, const float* __restrict__ W1,
                       const float* __restrict__ b1) {
    __shared__ float xs[8][IN_DIM];
    int r0 = blockIdx.x * 8;
    int t  = threadIdx.x;
    for (int i = t; i < 8 * IN_DIM; i += 256) {
        int r = i / IN_DIM, c = i % IN_DIM;
        xs[r][c] = x[(r0 + r) * IN_DIM + c];
    }
    __syncthreads();
    float acc[8];
    float bb = b1[t];
#pragma unroll
    for (int r = 0; r < 8; r++) acc[r] = bb;
    for (int i = 0; i < IN_DIM; i++) {
        float w = W1[i * HID + t];
#pragma unroll
        for (int r = 0; r < 8; r++) acc[r] += xs[r][i] * w;
    }
#pragma unroll
    for (int r = 0; r < 8; r++) {
        float a = acc[r];
        g_h[(r0 + r) * HID + t] = a / (1.f + expf(-a));   // SiLU
    }
}

// ---------------- Kernel B: theta = h @ W2 + b2 ----------------
// grid (64, 4): 8 batch rows x 1024-wide m tile per block
__global__ void k_mlp2(const float* __restrict__ W2, const float* __restrict__ b2) {
    __shared__ float hs[8][HID];
    int r0    = blockIdx.x * 8;
    int mbase = blockIdx.y * 1024;
    int t     = threadIdx.x;
    for (int i = t; i < 8 * HID; i += 256)
        hs[i / HID][i % HID] = g_h[(r0 + i / HID) * HID + (i % HID)];
    __syncthreads();
    for (int k = 0; k < 4; k++) {
        int m = mbase + t + 256 * k;
        if (m < NGEN) {
            float acc[8];
            float bb = b2[m];
#pragma unroll
            for (int r = 0; r < 8; r++) acc[r] = bb;
            for (int j = 0; j < HID; j++) {
                float w = W2[j * NGEN + m];
#pragma unroll
                for (int r = 0; r < 8; r++) acc[r] += hs[r][j] * w;
            }
#pragma unroll
            for (int r = 0; r < 8; r++) g_theta[(r0 + r) * NGEN + m] = acc[r];
        }
    }
}

// ---------------- Kernel C: build H via WHT, psi = exp(iH)e0, observables ----------------
// one block of 64 threads per batch element
__global__ void k_expq(const float* __restrict__ Aoff, const float* __restrict__ Boff,
                       const float* __restrict__ Ddiag) {
    __shared__ float Gre[64 * 64];   // [j][x] after WHT: Gre[j*64+x] = Hhat_x(j)
    __shared__ float Gim[64 * 64];
    __shared__ float ubr[2][64], ubi[2][64];
    __shared__ float psr[64], psi_[64];

    int b = blockIdx.x;
    int x = threadIdx.x;     // 0..63 : thread owns "x-row" then component x
    const float* th = g_theta + b * NGEN;

    // gather phased thetas into [z][x] layout
    for (int z = 0; z < 64; z++) {
        float re = 0.f, im = 0.f;
        if ((x | z) != 0) {
            int xz = x & z;
            int m = 0;
#pragma unroll
            for (int p = 0; p < 6; p++) {
                int l = ((x >> p) & 1) + 3 * ((z >> p) & 1) - 2 * ((xz >> p) & 1);
                m += l << (2 * p);
            }
            float tv = th[m - 1];
            int pc = __popc(xz) & 3;   // i^pc phase
            if      (pc == 0) re =  tv;
            else if (pc == 1) im =  tv;
            else if (pc == 2) re = -tv;
            else              im = -tv;
        }
        Gre[z * 64 + x] = re;
        Gim[z * 64 + x] = im;
    }
    // 64-point WHT along z, per column x (thread-private columns -> no syncs)
#pragma unroll
    for (int st = 0; st < 6; st++) {
        int hsz = 1 << st;
        for (int zb = 0; zb < 64; zb += (hsz << 1)) {
            for (int k = 0; k < hsz; k++) {
                int i0 = (zb + k) * 64 + x, i1 = (zb + k + hsz) * 64 + x;
                float ar = Gre[i0], ai = Gim[i0];
                float br = Gre[i1], bi = Gim[i1];
                Gre[i0] = ar + br; Gim[i0] = ai + bi;
                Gre[i1] = ar - br; Gim[i1] = ai - bi;
            }
        }
    }
    __syncthreads();
    // Now H[i][j] = Gre/Gim[j*64 + (i^j)]

    // psi = exp(iH) e0 via S substeps of degree-TDEG Taylor
    float vr = (x == 0) ? 1.f : 0.f, vi = 0.f;
    int buf = 0;
    for (int step = 0; step < SSTEPS; step++) {
        float ur = vr, ui = vi;
        float ar = vr, ai = vi;
#pragma unroll 1
        for (int t = 1; t <= TDEG; t++) {
            ubr[buf][x] = ur; ubi[buf][x] = ui;
            __syncthreads();
            float wr = 0.f, wi = 0.f;
#pragma unroll 16
            for (int j = 0; j < 64; j++) {
                int gidx = (j << 6) + (x ^ j);
                float gr = Gre[gidx], gi = Gim[gidx];
                float r2 = ubr[buf][j], i2 = ubi[buf][j];
                wr += gr * r2 - gi * i2;
                wi += gr * i2 + gi * r2;
            }
            float c = 1.f / (float)(SSTEPS * t);
            ur = -c * wi;            // u <- (i/(S t)) H u
            ui =  c * wr;
            ar += ur; ai += ui;
            buf ^= 1;                // double buffer: 1 sync per matvec
        }
        vr = ar; vi = ai;
    }
    psr[x] = vr; psi_[x] = vi;
    __syncthreads();

    // observables: threads 0..14, one wire pair each
    if (x < NOBS) {
        int a = PAIR_A[x], bw = PAIR_B[x];
        int pa = 5 - a, pb = 5 - bw;      // bit positions, pa > pb
        float dsum[4] = {0, 0, 0, 0};
        float orr[6] = {0, 0, 0, 0, 0, 0}, oii[6] = {0, 0, 0, 0, 0, 0};
        for (int r = 0; r < 16; r++) {
            int n0 = 0, rr = r;
#pragma unroll
            for (int p = 0; p < 6; p++) {
                if (p != pa && p != pb) { n0 |= (rr & 1) << p; rr >>= 1; }
            }
            float prk[4], pik[4];
#pragma unroll
            for (int k = 0; k < 4; k++) {
                int n = n0 | (((k >> 1) & 1) << pa) | ((k & 1) << pb);
                prk[k] = psr[n]; pik[k] = psi_[n];
            }
#pragma unroll
            for (int k = 0; k < 4; k++) dsum[k] += prk[k] * prk[k] + pik[k] * pik[k];
            int c = 0;
#pragma unroll
            for (int l = 1; l < 4; l++)
                for (int k = 0; k < l; k++) {
                    // rho_kl = psi_k conj(psi_l),  c = l(l-1)/2 + k
                    orr[c] += prk[k] * prk[l] + pik[k] * pik[l];
                    oii[c] += pik[k] * prk[l] - prk[k] * pik[l];
                    c++;
                }
        }
        float q = 0.f;
#pragma unroll
        for (int dd = 0; dd < 3; dd++) q += 2.f * Ddiag[x * 4 + dd + 1] * dsum[dd];
#pragma unroll
        for (int c = 0; c < 6; c++) {
            float A = Aoff[x * 6 + c], B = Boff[x * 6 + c];
            q += 2.f * (orr[c] * A - oii[c] * B);   // 2 Re(rho_kl * H_lk)
        }
        g_q[b * NOBS + x] = q;
    }
}

// ---------------- Kernel D: out = silu(q @ Wv1 + bv1) @ Wv2 + bv2, 4 rows/block ----------------
__global__ void k_head(const float* __restrict__ Wv1, const float* __restrict__ bv1,
                       const float* __restrict__ Wv2, const float* __restrict__ bv2,
                       float* __restrict__ out) {
    __shared__ float qs[4][NOBS];
    __shared__ float hh[4][HID];
    int r0 = blockIdx.x * 4, t = threadIdx.x;
    if (t < 4 * NOBS) qs[t / NOBS][t % NOBS] = g_q[(r0 + t / NOBS) * NOBS + t % NOBS];
    __syncthreads();
    float a[4];
    float bb = bv1[t];
#pragma unroll
    for (int r = 0; r < 4; r++) a[r] = bb;
    for (int j = 0; j < NOBS; j++) {
        float w = Wv1[j * HID + t];
#pragma unroll
        for (int r = 0; r < 4; r++) a[r] += qs[r][j] * w;
    }
#pragma unroll
    for (int r = 0; r < 4; r++) hh[r][t] = a[r] / (1.f + expf(-a[r]));
    __syncthreads();
    for (int kk = 0; kk < 2; kk++) {
        int o = t + 256 * kk;
        float acc[4];
        float bo = bv2[o];
#pragma unroll
        for (int r = 0; r < 4; r++) acc[r] = bo;
        for (int j = 0; j < HID; j++) {
            float w = Wv2[j * OUT_DIM + o];
#pragma unroll
            for (int r = 0; r < 4; r++) acc[r] += hh[r][j] * w;
        }
#pragma unroll
        for (int r = 0; r < 4; r++) out[(r0 + r) * OUT_DIM + o] = acc[r];
    }
}

extern "C" void kernel_launch(void* const* d_in, const int* in_sizes, int n_in,
                              void* d_out, int out_size) {
    const float* x    = (const float*)d_in[0];
    const float* W1   = (const float*)d_in[1];
    const float* b1   = (const float*)d_in[2];
    const float* W2   = (const float*)d_in[3];
    const float* b2   = (const float*)d_in[4];
    const float* Aoff = (const float*)d_in[5];
    const float* Boff = (const float*)d_in[6];
    const float* Dd   = (const float*)d_in[7];
    const float* Wv1  = (const float*)d_in[8];
    const float* bv1  = (const float*)d_in[9];
    const float* Wv2  = (const float*)d_in[10];
    const float* bv2  = (const float*)d_in[11];
    // d_in[12] = pauli basis: not needed (Pauli structure is computed analytically)
    float* out = (float*)d_out;

    k_mlp1<<<BATCH / 8, 256>>>(x, W1, b1);
    dim3 g2(BATCH / 8, 4);
    k_mlp2<<<g2, 256>>>(W2, b2);
    k_expq<<<BATCH, 64>>>(Aoff, Boff, Dd);
    k_head<<<BATCH / 4, 256>>>(Wv1, bv1, Wv2, bv2, out);
}

// round 3
// speedup vs baseline: 1.9634x; 1.9634x over previous
#include <cuda_runtime.h>
#include <math.h>

#define BATCH   512
#define IN_DIM  768
#define HID     256
#define NGEN    4095
#define NOBS    15
#define OUT_DIM 512
#define DIM     64
#define TDEG    12

// -------- scratch (static device globals; no runtime allocation) --------
__device__ float g_h[BATCH * HID];        // hidden of enc MLP
__device__ float g_theta[BATCH * NGEN];   // SU(64) angles
__device__ float g_q[BATCH * NOBS];       // expectation values

__device__ const int PAIR_A[15] = {0,0,0,0,0,1,1,1,1,2,2,2,3,3,4};
__device__ const int PAIR_B[15] = {1,2,3,4,5,2,3,4,5,3,4,5,4,5,5};
__constant__ float RT_TAB[TDEG + 1] = {0.f, 1.f, 1.f/2, 1.f/3, 1.f/4, 1.f/5, 1.f/6,
                                       1.f/7, 1.f/8, 1.f/9, 1.f/10, 1.f/11, 1.f/12};

// ---------------- Kernel A: h = silu(x @ W1 + b1), 8 rows/block ----------------
__global__ void k_mlp1(const float* __restrict__ x, const float* __restrict__ W1,
                       const float* __restrict__ b1) {
    __shared__ float xs[8][IN_DIM];
    int r0 = blockIdx.x * 8;
    int t  = threadIdx.x;
    for (int i = t; i < 8 * IN_DIM; i += 256) {
        int r = i / IN_DIM, c = i % IN_DIM;
        xs[r][c] = x[(r0 + r) * IN_DIM + c];
    }
    __syncthreads();
    float acc[8];
    float bb = b1[t];
#pragma unroll
    for (int r = 0; r < 8; r++) acc[r] = bb;
    for (int i = 0; i < IN_DIM; i++) {
        float w = W1[i * HID + t];
#pragma unroll
        for (int r = 0; r < 8; r++) acc[r] += xs[r][i] * w;
    }
#pragma unroll
    for (int r = 0; r < 8; r++) {
        float a = acc[r];
        g_h[(r0 + r) * HID + t] = a / (1.f + expf(-a));   // SiLU
    }
}

// ---------------- Kernel B: theta = h @ W2 + b2, 16 rows x 1024-col tile ----------------
__global__ void k_mlp2(const float* __restrict__ W2, const float* __restrict__ b2) {
    __shared__ float hs[16][HID];
    int r0    = blockIdx.x * 16;
    int mbase = blockIdx.y * 1024;
    int t     = threadIdx.x;
    for (int i = t; i < 16 * HID; i += 256)
        hs[i / HID][i % HID] = g_h[(r0 + i / HID) * HID + (i % HID)];
    __syncthreads();
    for (int k = 0; k < 4; k++) {
        int m = mbase + t + 256 * k;
        if (m < NGEN) {
            float acc[16];
            float bb = b2[m];
#pragma unroll
            for (int r = 0; r < 16; r++) acc[r] = bb;
            for (int j = 0; j < HID; j++) {
                float w = W2[j * NGEN + m];
#pragma unroll
                for (int r = 0; r < 16; r++) acc[r] += hs[r][j] * w;
            }
#pragma unroll
            for (int r = 0; r < 16; r++) g_theta[(r0 + r) * NGEN + m] = acc[r];
        }
    }
}

// ---------------- Kernel C: build H via WHT, psi = exp(iH)e0, observables ----------------
// one block of 64 threads per batch element; H row x lives in thread-x registers
__global__ void __launch_bounds__(64) k_expq(const float* __restrict__ Aoff,
                                             const float* __restrict__ Boff,
                                             const float* __restrict__ Ddiag) {
    __shared__ float Gre[64 * 64];   // [z][x] pre-WHT; [j][x] post-WHT (Hhat)
    __shared__ float Gim[64 * 64];
    __shared__ float2 us[2][64];     // double-buffered u vector
    __shared__ float psr[64], psi_[64];
    __shared__ float sred[2];

    int b = blockIdx.x;
    int x = threadIdx.x;     // 0..63
    const float* th = g_theta + b * NGEN;

    // gather phased thetas into [z][x] layout; accumulate sum(theta^2)
    float s2 = 0.f;
    for (int z = 0; z < 64; z++) {
        float re = 0.f, im = 0.f;
        if ((x | z) != 0) {
            int xz = x & z;
            int m = 0;
#pragma unroll
            for (int p = 0; p < 6; p++) {
                int l = ((x >> p) & 1) + 3 * ((z >> p) & 1) - 2 * ((xz >> p) & 1);
                m += l << (2 * p);
            }
            float tv = th[m - 1];
            s2 += tv * tv;
            int pc = __popc(xz) & 3;   // i^pc phase
            if      (pc == 0) re =  tv;
            else if (pc == 1) im =  tv;
            else if (pc == 2) re = -tv;
            else              im = -tv;
        }
        Gre[z * 64 + x] = re;
        Gim[z * 64 + x] = im;
    }
    // warp-reduce s2 -> sred
#pragma unroll
    for (int m = 16; m > 0; m >>= 1) s2 += __shfl_xor_sync(0xffffffffu, s2, m);
    if ((x & 31) == 0) sred[x >> 5] = s2;

    // 64-point WHT along z, per column x (thread-private column -> no syncs)
#pragma unroll
    for (int st = 0; st < 6; st++) {
        int hsz = 1 << st;
        for (int zb = 0; zb < 64; zb += (hsz << 1)) {
            for (int k = 0; k < hsz; k++) {
                int i0 = (zb + k) * 64 + x, i1 = (zb + k + hsz) * 64 + x;
                float ar = Gre[i0], ai = Gim[i0];
                float br = Gre[i1], bi = Gim[i1];
                Gre[i0] = ar + br; Gim[i0] = ai + bi;
                Gre[i1] = ar - br; Gim[i1] = ai - bi;
            }
        }
    }
    __syncthreads();
    // H[i][j] = G[j*64 + (i^j)]  -> load row x into registers (conflict-free: low5(x^j) distinct)
    float Hr[64], Hi[64];
#pragma unroll
    for (int j = 0; j < 64; j++) {
        int gi = (j << 6) + (x ^ j);
        Hr[j] = Gre[gi];
        Hi[j] = Gim[gi];
    }

    // adaptive substep count: spectral edge a ~= 2*sqrt(sum theta^2), 15% margin, z_max=2
    float a_edge = 2.f * sqrtf(sred[0] + sred[1]);
    int S = (int)ceilf(a_edge * 0.575f);
    if (S < 1) S = 1;
    float invS = 1.f / (float)S;

    // psi = exp(iH) e0 via S substeps of degree-TDEG Taylor; 1 sync per matvec
    float vr = (x == 0) ? 1.f : 0.f, vi = 0.f;
    int buf = 0;
    for (int step = 0; step < S; step++) {
        float ur = vr, ui = vi;
        float ar = vr, ai = vi;
#pragma unroll 1
        for (int t = 1; t <= TDEG; t++) {
            us[buf][x] = make_float2(ur, ui);
            __syncthreads();
            float wr = 0.f, wi = 0.f;
#pragma unroll
            for (int j = 0; j < 64; j++) {
                float2 u2 = us[buf][j];           // broadcast
                wr = fmaf(Hr[j], u2.x, wr);
                wr = fmaf(-Hi[j], u2.y, wr);
                wi = fmaf(Hr[j], u2.y, wi);
                wi = fmaf(Hi[j], u2.x, wi);
            }
            float c = invS * RT_TAB[t];
            ur = -c * wi;            // u <- (i/(S t)) H u
            ui =  c * wr;
            ar += ur; ai += ui;
            buf ^= 1;                // double buffer: 1 sync per matvec
        }
        vr = ar; vi = ai;
    }
    psr[x] = vr; psi_[x] = vi;
    __syncthreads();

    // observables: threads 0..14, one wire pair each
    if (x < NOBS) {
        int a = PAIR_A[x], bw = PAIR_B[x];
        int pa = 5 - a, pb = 5 - bw;      // bit positions, pa > pb
        float dsum[4] = {0, 0, 0, 0};
        float orr[6] = {0, 0, 0, 0, 0, 0}, oii[6] = {0, 0, 0, 0, 0, 0};
        for (int r = 0; r < 16; r++) {
            int n0 = 0, rr = r;
#pragma unroll
            for (int p = 0; p < 6; p++) {
                if (p != pa && p != pb) { n0 |= (rr & 1) << p; rr >>= 1; }
            }
            float prk[4], pik[4];
#pragma unroll
            for (int k = 0; k < 4; k++) {
                int n = n0 | (((k >> 1) & 1) << pa) | ((k & 1) << pb);
                prk[k] = psr[n]; pik[k] = psi_[n];
            }
#pragma unroll
            for (int k = 0; k < 4; k++) dsum[k] += prk[k] * prk[k] + pik[k] * pik[k];
            int c = 0;
#pragma unroll
            for (int l = 1; l < 4; l++)
                for (int k = 0; k < l; k++) {
                    orr[c] += prk[k] * prk[l] + pik[k] * pik[l];
                    oii[c] += pik[k] * prk[l] - prk[k] * pik[l];
                    c++;
                }
        }
        float q = 0.f;
#pragma unroll
        for (int dd = 0; dd < 3; dd++) q += 2.f * Ddiag[x * 4 + dd + 1] * dsum[dd];
#pragma unroll
        for (int c = 0; c < 6; c++) {
            float A = Aoff[x * 6 + c], B = Boff[x * 6 + c];
            q += 2.f * (orr[c] * A - oii[c] * B);   // 2 Re(rho_kl * H_lk)
        }
        g_q[b * NOBS + x] = q;
    }
}

// ---------------- Kernel D: out = silu(q @ Wv1 + bv1) @ Wv2 + bv2 ----------------
// 4 rows/block, 512 threads (16 warps) for latency hiding
__global__ void k_head(const float* __restrict__ Wv1, const float* __restrict__ bv1,
                       const float* __restrict__ Wv2, const float* __restrict__ bv2,
                       float* __restrict__ out) {
    __shared__ float qs[4][NOBS];
    __shared__ float hh[4][HID];
    int r0 = blockIdx.x * 4, t = threadIdx.x;
    if (t < 4 * NOBS) qs[t / NOBS][t % NOBS] = g_q[(r0 + t / NOBS) * NOBS + t % NOBS];
    __syncthreads();
    if (t < HID) {
        float a[4];
        float bb = bv1[t];
#pragma unroll
        for (int r = 0; r < 4; r++) a[r] = bb;
#pragma unroll
        for (int j = 0; j < NOBS; j++) {
            float w = Wv1[j * HID + t];
#pragma unroll
            for (int r = 0; r < 4; r++) a[r] += qs[r][j] * w;
        }
#pragma unroll
        for (int r = 0; r < 4; r++) hh[r][t] = a[r] / (1.f + expf(-a[r]));
    }
    __syncthreads();
    int o = t;   // 0..511
    float acc[4];
    float bo = bv2[o];
#pragma unroll
    for (int r = 0; r < 4; r++) acc[r] = bo;
#pragma unroll 8
    for (int j = 0; j < HID; j++) {
        float w = Wv2[j * OUT_DIM + o];
#pragma unroll
        for (int r = 0; r < 4; r++) acc[r] += hh[r][j] * w;
    }
#pragma unroll
    for (int r = 0; r < 4; r++) out[(r0 + r) * OUT_DIM + o] = acc[r];
}

extern "C" void kernel_launch(void* const* d_in, const int* in_sizes, int n_in,
                              void* d_out, int out_size) {
    const float* x    = (const float*)d_in[0];
    const float* W1   = (const float*)d_in[1];
    const float* b1   = (const float*)d_in[2];
    const float* W2   = (const float*)d_in[3];
    const float* b2   = (const float*)d_in[4];
    const float* Aoff = (const float*)d_in[5];
    const float* Boff = (const float*)d_in[6];
    const float* Dd   = (const float*)d_in[7];
    const float* Wv1  = (const float*)d_in[8];
    const float* bv1  = (const float*)d_in[9];
    const float* Wv2  = (const float*)d_in[10];
    const float* bv2  = (const float*)d_in[11];
    // d_in[12] = pauli basis: unused (Pauli structure computed analytically)
    float* out = (float*)d_out;

    k_mlp1<<<BATCH / 8, 256>>>(x, W1, b1);
    dim3 g2(BATCH / 16, 4);
    k_mlp2<<<g2, 256>>>(W2, b2);
    k_expq<<<BATCH, 64>>>(Aoff, Boff, Dd);
    k_head<<<BATCH / 4, 512>>>(Wv1, bv1, Wv2, bv2, out);
}

// round 4
// speedup vs baseline: 2.5888x; 1.3185x over previous
#include <cuda_runtime.h>
#include <math.h>

#define BATCH   512
#define IN_DIM  768
#define HID     256
#define NGEN    4095
#define NOBS    15
#define OUT_DIM 512
#define DIM     64
#define CFMAX   256

// -------- scratch (static device globals; no runtime allocation) --------
__device__ float g_h[BATCH * HID];        // hidden of enc MLP
__device__ float g_theta[BATCH * NGEN];   // SU(64) angles
__device__ float g_q[BATCH * NOBS];       // expectation values

__device__ const int PAIR_A[15] = {0,0,0,0,0,1,1,1,1,2,2,2,3,3,4};
__device__ const int PAIR_B[15] = {1,2,3,4,5,2,3,4,5,3,4,5,4,5,5};

// ---------------- Kernel A: h = silu(x @ W1 + b1), 8 rows/block ----------------
__global__ void k_mlp1(const float* __restrict__ x, const float* __restrict__ W1,
                       const float* __restrict__ b1) {
    __shared__ float xs[8][IN_DIM];
    int r0 = blockIdx.x * 8;
    int t  = threadIdx.x;
    for (int i = t; i < 8 * IN_DIM; i += 256) {
        int r = i / IN_DIM, c = i % IN_DIM;
        xs[r][c] = x[(r0 + r) * IN_DIM + c];
    }
    __syncthreads();
    float acc[8];
    float bb = b1[t];
#pragma unroll
    for (int r = 0; r < 8; r++) acc[r] = bb;
#pragma unroll 2
    for (int i = 0; i < IN_DIM; i += 4) {
        float w0 = W1[(i + 0) * HID + t];
        float w1 = W1[(i + 1) * HID + t];
        float w2 = W1[(i + 2) * HID + t];
        float w3 = W1[(i + 3) * HID + t];
#pragma unroll
        for (int r = 0; r < 8; r++) {
            float4 xv = *(const float4*)&xs[r][i];   // LDS.128 broadcast
            acc[r] = fmaf(xv.x, w0, acc[r]);
            acc[r] = fmaf(xv.y, w1, acc[r]);
            acc[r] = fmaf(xv.z, w2, acc[r]);
            acc[r] = fmaf(xv.w, w3, acc[r]);
        }
    }
#pragma unroll
    for (int r = 0; r < 8; r++) {
        float a = acc[r];
        g_h[(r0 + r) * HID + t] = a / (1.f + expf(-a));   // SiLU
    }
}

// ---------------- Kernel B: theta = h @ W2 + b2, 16 rows x 1024-col tile ----------------
__global__ void k_mlp2(const float* __restrict__ W2, const float* __restrict__ b2) {
    __shared__ float hs[16][HID];
    int r0    = blockIdx.x * 16;
    int mbase = blockIdx.y * 1024;
    int t     = threadIdx.x;
    for (int i = t; i < 16 * HID; i += 256)
        hs[i / HID][i % HID] = g_h[(r0 + i / HID) * HID + (i % HID)];
    __syncthreads();
    for (int k = 0; k < 4; k++) {
        int m = mbase + t + 256 * k;
        if (m < NGEN) {
            float acc[16];
            float bb = b2[m];
#pragma unroll
            for (int r = 0; r < 16; r++) acc[r] = bb;
#pragma unroll 1
            for (int j = 0; j < HID; j += 4) {
                float w0 = W2[(j + 0) * NGEN + m];
                float w1 = W2[(j + 1) * NGEN + m];
                float w2 = W2[(j + 2) * NGEN + m];
                float w3 = W2[(j + 3) * NGEN + m];
#pragma unroll
                for (int r = 0; r < 16; r++) {
                    float4 hv = *(const float4*)&hs[r][j];   // LDS.128 broadcast
                    acc[r] = fmaf(hv.x, w0, acc[r]);
                    acc[r] = fmaf(hv.y, w1, acc[r]);
                    acc[r] = fmaf(hv.z, w2, acc[r]);
                    acc[r] = fmaf(hv.w, w3, acc[r]);
                }
            }
#pragma unroll
            for (int r = 0; r < 16; r++) g_theta[(r0 + r) * NGEN + m] = acc[r];
        }
    }
}

// ---------------- Kernel C: H via WHT, psi = exp(iH)e0 (Chebyshev), observables ----------------
// one block of 64 threads per batch element; H row x lives in thread-x registers
__global__ void __launch_bounds__(64) k_expq(const float* __restrict__ Aoff,
                                             const float* __restrict__ Boff,
                                             const float* __restrict__ Ddiag) {
    __shared__ float Gre[64 * 64];   // [z][x] pre-WHT; [j][x] post-WHT
    __shared__ float Gim[64 * 64];
    __shared__ float2 us[2][64];     // double-buffered Chebyshev vector
    __shared__ float psr[64], psi_[64];
    __shared__ float sred[2];
    __shared__ float cf[CFMAX];      // unnormalized Bessel J_k (Miller)

    int b = blockIdx.x;
    int x = threadIdx.x;     // 0..63
    const float* th = g_theta + b * NGEN;

    // gather phased thetas into [z][x] layout; accumulate sum(theta^2)
    float s2 = 0.f;
    for (int z = 0; z < 64; z++) {
        float re = 0.f, im = 0.f;
        if ((x | z) != 0) {
            int xz = x & z;
            int m = 0;
#pragma unroll
            for (int p = 0; p < 6; p++) {
                int l = ((x >> p) & 1) + 3 * ((z >> p) & 1) - 2 * ((xz >> p) & 1);
                m += l << (2 * p);
            }
            float tv = th[m - 1];
            s2 += tv * tv;
            int pc = __popc(xz) & 3;   // i^pc phase
            if      (pc == 0) re =  tv;
            else if (pc == 1) im =  tv;
            else if (pc == 2) re = -tv;
            else              im = -tv;
        }
        Gre[z * 64 + x] = re;
        Gim[z * 64 + x] = im;
    }
#pragma unroll
    for (int m = 16; m > 0; m >>= 1) s2 += __shfl_xor_sync(0xffffffffu, s2, m);
    if ((x & 31) == 0) sred[x >> 5] = s2;

    // 64-point WHT along z, per column x (thread-private -> no syncs)
#pragma unroll
    for (int st = 0; st < 6; st++) {
        int hsz = 1 << st;
        for (int zb = 0; zb < 64; zb += (hsz << 1)) {
            for (int k = 0; k < hsz; k++) {
                int i0 = (zb + k) * 64 + x, i1 = (zb + k + hsz) * 64 + x;
                float ar = Gre[i0], ai = Gim[i0];
                float br = Gre[i1], bi = Gim[i1];
                Gre[i0] = ar + br; Gim[i0] = ai + bi;
                Gre[i1] = ar - br; Gim[i1] = ai - bi;
            }
        }
    }
    __syncthreads();
    // H[i][j] = G[j*64 + (i^j)] -> row x into registers (conflict-free: low5(x^j) distinct)
    float Hr[64], Hi[64];
#pragma unroll
    for (int j = 0; j < 64; j++) {
        int gi = (j << 6) + (x ^ j);
        Hr[j] = Gre[gi];
        Hi[j] = Gim[gi];
    }

    // Chebyshev interval: a' = 1.35 * semicircle edge, clamped >= 4 (Miller stability)
    float ap = 2.7f * sqrtf(sred[0] + sred[1]);
    if (ap < 4.f) ap = 4.f;
    float inva = 1.f / ap;
    int K = (int)ceilf(ap + 8.f * cbrtf(ap) + 4.f);
    if (K > CFMAX - 20) K = CFMAX - 20;
    int mstart = K + 12; mstart += (mstart & 1);   // even start

    // Miller downward recurrence for J_k(ap), all threads redundant, thread 0 stores
    {
        float jkp1 = 0.f, jk = 1e-20f, sum = 0.f;
        for (int k = mstart; k >= 1; --k) {
            if (k < CFMAX && x == 0) cf[k] = jk;
            if ((k & 1) == 0) sum += 2.f * jk;
            float jkm1 = fmaf(2.f * (float)k * inva, jk, -jkp1);
            jkp1 = jk; jk = jkm1;
        }
        if (x == 0) cf[0] = jk;
        sum += jk;
        psr[0] = 1.f / sum;          // stash invnorm (overwritten later)
    }
    __syncthreads();
    float invn = psr[0];
    __syncthreads();

    // psi = sum_k i^k (2-d_k0) J_k(ap) T_k(H/ap) e0   (Clenshaw-free 3-term recurrence)
    float tpr = (x == 0) ? 1.f : 0.f, tpi = 0.f;       // T_0 e0
    float tcr = Hr[0] * inva, tci = Hi[0] * inva;      // T_1 e0 = (H/ap) e0
    float g0 = cf[0] * invn;
    float accr = g0 * tpr, acci = 0.f;
    {
        float g1 = 2.f * cf[1] * invn;                 // phase i^1
        accr = fmaf(-g1, tci, accr);
        acci = fmaf( g1, tcr, acci);
    }
    float twoinva = 2.f * inva;
    int buf = 0;
#pragma unroll 1
    for (int k = 2; k <= K; k++) {
        us[buf][x] = make_float2(tcr, tci);
        __syncthreads();
        float wr0 = 0.f, wi0 = 0.f, wr1 = 0.f, wi1 = 0.f;
#pragma unroll
        for (int j = 0; j < 64; j += 2) {
            float2 u0 = us[buf][j];
            float2 u1 = us[buf][j + 1];
            wr0 = fmaf(Hr[j],     u0.x, wr0); wr0 = fmaf(-Hi[j],     u0.y, wr0);
            wi0 = fmaf(Hr[j],     u0.y, wi0); wi0 = fmaf( Hi[j],     u0.x, wi0);
            wr1 = fmaf(Hr[j + 1], u1.x, wr1); wr1 = fmaf(-Hi[j + 1], u1.y, wr1);
            wi1 = fmaf(Hr[j + 1], u1.y, wi1); wi1 = fmaf( Hi[j + 1], u1.x, wi1);
        }
        float wr = wr0 + wr1, wi = wi0 + wi1;
        float tnr = fmaf(twoinva, wr, -tpr);
        float tni = fmaf(twoinva, wi, -tpi);
        tpr = tcr; tpi = tci; tcr = tnr; tci = tni;
        // c_k = i^k * 2 J_k : phase via (gr + i gi)
        float g = 2.f * cf[k] * invn;
        int p = k & 3;
        float gr = (p == 0) ? g : ((p == 2) ? -g : 0.f);
        float gi = (p == 1) ? g : ((p == 3) ? -g : 0.f);
        accr = fmaf(gr, tcr, accr); accr = fmaf(-gi, tci, accr);
        acci = fmaf(gr, tci, acci); acci = fmaf( gi, tcr, acci);
        buf ^= 1;
    }
    __syncthreads();
    psr[x] = accr; psi_[x] = acci;
    __syncthreads();

    // observables: threads 0..14, one wire pair each
    if (x < NOBS) {
        int a = PAIR_A[x], bw = PAIR_B[x];
        int pa = 5 - a, pb = 5 - bw;
        float dsum[4] = {0, 0, 0, 0};
        float orr[6] = {0, 0, 0, 0, 0, 0}, oii[6] = {0, 0, 0, 0, 0, 0};
        for (int r = 0; r < 16; r++) {
            int n0 = 0, rr = r;
#pragma unroll
            for (int p = 0; p < 6; p++) {
                if (p != pa && p != pb) { n0 |= (rr & 1) << p; rr >>= 1; }
            }
            float prk[4], pik[4];
#pragma unroll
            for (int k = 0; k < 4; k++) {
                int n = n0 | (((k >> 1) & 1) << pa) | ((k & 1) << pb);
                prk[k] = psr[n]; pik[k] = psi_[n];
            }
#pragma unroll
            for (int k = 0; k < 4; k++) dsum[k] += prk[k] * prk[k] + pik[k] * pik[k];
            int c = 0;
#pragma unroll
            for (int l = 1; l < 4; l++)
                for (int k = 0; k < l; k++) {
                    orr[c] += prk[k] * prk[l] + pik[k] * pik[l];
                    oii[c] += pik[k] * prk[l] - prk[k] * pik[l];
                    c++;
                }
        }
        float q = 0.f;
#pragma unroll
        for (int dd = 0; dd < 3; dd++) q += 2.f * Ddiag[x * 4 + dd + 1] * dsum[dd];
#pragma unroll
        for (int c = 0; c < 6; c++) {
            float A = Aoff[x * 6 + c], B = Boff[x * 6 + c];
            q += 2.f * (orr[c] * A - oii[c] * B);
        }
        g_q[b * NOBS + x] = q;
    }
}

// ---------------- Kernel D: out = silu(q @ Wv1 + bv1) @ Wv2 + bv2 ----------------
// grid (BATCH/4, 2): 4 rows x 256-col half per block; Wv2 staged in shared tiles
__global__ void k_head(const float* __restrict__ Wv1, const float* __restrict__ bv1,
                       const float* __restrict__ Wv2, const float* __restrict__ bv2,
                       float* __restrict__ out) {
    __shared__ float qs[4][NOBS];
    __shared__ float4 hh4[HID];          // 4 rows packed per hidden unit
    __shared__ float wv[32][256];        // Wv2 tile
    int r0 = blockIdx.x * 4, half = blockIdx.y, t = threadIdx.x;
    if (t < 4 * NOBS) qs[t / NOBS][t % NOBS] = g_q[(r0 + t / NOBS) * NOBS + t % NOBS];
    __syncthreads();
    // hidden unit t for 4 rows
    {
        float a0 = bv1[t], a1 = a0, a2 = a0, a3 = a0;
#pragma unroll
        for (int j = 0; j < NOBS; j++) {
            float w = Wv1[j * HID + t];
            a0 = fmaf(qs[0][j], w, a0);
            a1 = fmaf(qs[1][j], w, a1);
            a2 = fmaf(qs[2][j], w, a2);
            a3 = fmaf(qs[3][j], w, a3);
        }
        hh4[t] = make_float4(a0 / (1.f + expf(-a0)), a1 / (1.f + expf(-a1)),
                             a2 / (1.f + expf(-a2)), a3 / (1.f + expf(-a3)));
    }
    __syncthreads();
    int o = half * 256 + t;
    float acc0 = bv2[o], acc1 = acc0, acc2 = acc0, acc3 = acc0;
    for (int kt = 0; kt < 8; kt++) {
        for (int i = t; i < 32 * 256; i += 256) {
            int row = i >> 8, col = i & 255;
            wv[row][col] = Wv2[(kt * 32 + row) * OUT_DIM + half * 256 + col];
        }
        __syncthreads();
#pragma unroll
        for (int jj = 0; jj < 32; jj++) {
            float4 h = hh4[kt * 32 + jj];   // LDS.128 broadcast
            float w = wv[jj][t];
            acc0 = fmaf(h.x, w, acc0);
            acc1 = fmaf(h.y, w, acc1);
            acc2 = fmaf(h.z, w, acc2);
            acc3 = fmaf(h.w, w, acc3);
        }
        __syncthreads();
    }
    out[(r0 + 0) * OUT_DIM + o] = acc0;
    out[(r0 + 1) * OUT_DIM + o] = acc1;
    out[(r0 + 2) * OUT_DIM + o] = acc2;
    out[(r0 + 3) * OUT_DIM + o] = acc3;
}

extern "C" void kernel_launch(void* const* d_in, const int* in_sizes, int n_in,
                              void* d_out, int out_size) {
    const float* x    = (const float*)d_in[0];
    const float* W1   = (const float*)d_in[1];
    const float* b1   = (const float*)d_in[2];
    const float* W2   = (const float*)d_in[3];
    const float* b2   = (const float*)d_in[4];
    const float* Aoff = (const float*)d_in[5];
    const float* Boff = (const float*)d_in[6];
    const float* Dd   = (const float*)d_in[7];
    const float* Wv1  = (const float*)d_in[8];
    const float* bv1  = (const float*)d_in[9];
    const float* Wv2  = (const float*)d_in[10];
    const float* bv2  = (const float*)d_in[11];
    // d_in[12] = pauli basis: unused (Pauli structure computed analytically)
    float* out = (float*)d_out;

    k_mlp1<<<BATCH / 8, 256>>>(x, W1, b1);
    dim3 g2(BATCH / 16, 4);
    k_mlp2<<<g2, 256>>>(W2, b2);
    k_expq<<<BATCH, 64>>>(Aoff, Boff, Dd);
    dim3 gh(BATCH / 4, 2);
    k_head<<<gh, 256>>>(Wv1, bv1, Wv2, bv2, out);
}

// round 5
// speedup vs baseline: 3.1100x; 1.2013x over previous
#include <cuda_runtime.h>
#include <math.h>

#define BATCH   512
#define IN_DIM  768
#define HID     256
#define NGEN    4095
#define NOBS    15
#define OUT_DIM 512
#define DIM     64
#define CFMAX   256

typedef unsigned long long ull;

// -------- scratch (static device globals; no runtime allocation) --------
__device__ float g_h[BATCH * HID];        // hidden of enc MLP
__device__ float g_theta[BATCH * NGEN];   // SU(64) angles
__device__ float g_hh[BATCH * HID];       // hidden of vel head (head1 fused in expq)
__device__ int   g_idx[DIM * DIM];        // (m-1) | (phase<<16) Pauli gather table

__device__ const int PAIR_A[15] = {0,0,0,0,0,1,1,1,1,2,2,2,3,3,4};
__device__ const int PAIR_B[15] = {1,2,3,4,5,2,3,4,5,3,4,5,4,5,5};

// ---- f32x2 helpers ----
__device__ __forceinline__ ull pk2(float lo, float hi) {
    ull r; asm("mov.b64 %0, {%1,%2};" : "=l"(r) : "f"(lo), "f"(hi)); return r;
}
__device__ __forceinline__ void fma2(ull& d, ull a, ull b) {
    asm("fma.rn.f32x2 %0, %1, %2, %0;" : "+l"(d) : "l"(a), "l"(b));
}
__device__ __forceinline__ float2 up2(ull v) {
    float2 f; asm("mov.b64 {%0,%1}, %2;" : "=f"(f.x), "=f"(f.y) : "l"(v)); return f;
}

// ---------------- Kernel 0: Pauli gather index table (recomputed each call) ----------------
__global__ void k_init_idx() {
    int i = blockIdx.x * 256 + threadIdx.x;   // 0..4095
    int x = i & 63, z = i >> 6;
    int m = 0;
#pragma unroll
    for (int p = 0; p < 6; p++) {
        int l = ((x >> p) & 1) + 3 * ((z >> p) & 1) - 2 * (((x & z) >> p) & 1);
        m += l << (2 * p);
    }
    int pc = __popc(x & z) & 3;
    g_idx[i] = (i == 0) ? 0 : ((m - 1) | (pc << 16));
}

// ---------------- Kernel A: h = silu(x @ W1 + b1), 8 rows/block ----------------
__global__ void k_mlp1(const float* __restrict__ x, const float* __restrict__ W1,
                       const float* __restrict__ b1) {
    __shared__ float xs[8][IN_DIM];
    int r0 = blockIdx.x * 8;
    int t  = threadIdx.x;
    for (int i = t; i < 8 * IN_DIM; i += 256) {
        int r = i / IN_DIM, c = i % IN_DIM;
        xs[r][c] = x[(r0 + r) * IN_DIM + c];
    }
    __syncthreads();
    float acc[8];
    float bb = b1[t];
#pragma unroll
    for (int r = 0; r < 8; r++) acc[r] = bb;
#pragma unroll 2
    for (int i = 0; i < IN_DIM; i += 4) {
        float w0 = W1[(i + 0) * HID + t];
        float w1 = W1[(i + 1) * HID + t];
        float w2 = W1[(i + 2) * HID + t];
        float w3 = W1[(i + 3) * HID + t];
#pragma unroll
        for (int r = 0; r < 8; r++) {
            float4 xv = *(const float4*)&xs[r][i];
            acc[r] = fmaf(xv.x, w0, acc[r]);
            acc[r] = fmaf(xv.y, w1, acc[r]);
            acc[r] = fmaf(xv.z, w2, acc[r]);
            acc[r] = fmaf(xv.w, w3, acc[r]);
        }
    }
#pragma unroll
    for (int r = 0; r < 8; r++) {
        float a = acc[r];
        g_h[(r0 + r) * HID + t] = a / (1.f + expf(-a));
    }
}

// ---------------- Kernel B: theta = h @ W2 + b2 (f32x2), 16 rows x 1024-col ----------------
#define PADR 20   // row stride of transposed tile (16B-aligned, mild store conflicts)
__global__ void k_mlp2(const float* __restrict__ W2, const float* __restrict__ b2) {
    __shared__ float hsT[HID][PADR];   // transposed: hsT[j][r]
    int r0    = blockIdx.x * 16;
    int mbase = blockIdx.y * 1024;
    int t     = threadIdx.x;
    for (int i = t; i < 16 * HID; i += 256) {
        int j = i & 255, r = i >> 8;
        hsT[j][r] = g_h[(r0 + r) * HID + j];   // coalesced LDG
    }
    __syncthreads();
    for (int k = 0; k < 4; k++) {
        int m = mbase + t + 256 * k;
        if (m < NGEN) {
            float bb = b2[m];
            ull acc[8];
#pragma unroll
            for (int p = 0; p < 8; p++) acc[p] = pk2(bb, bb);
            acc[1] = pk2(0.f, 0.f); acc[2] = pk2(0.f, 0.f); acc[3] = pk2(0.f, 0.f);
            acc[5] = pk2(0.f, 0.f); acc[6] = pk2(0.f, 0.f); acc[7] = pk2(0.f, 0.f);
#pragma unroll 2
            for (int j = 0; j < HID; j += 2) {
                float w0 = W2[(j + 0) * NGEN + m];
                float w1 = W2[(j + 1) * NGEN + m];
                ull wd0 = pk2(w0, w0), wd1 = pk2(w1, w1);
#pragma unroll
                for (int p = 0; p < 4; p++) {
                    longlong2 h0 = *(const longlong2*)&hsT[j][4 * p];       // 2 row-pairs
                    longlong2 h1 = *(const longlong2*)&hsT[j + 1][4 * p];
                    fma2(acc[2 * p],     (ull)h0.x, wd0);
                    fma2(acc[2 * p + 1], (ull)h0.y, wd0);
                    fma2(acc[2 * p],     (ull)h1.x, wd1);
                    fma2(acc[2 * p + 1], (ull)h1.y, wd1);
                }
            }
#pragma unroll
            for (int p = 0; p < 8; p++) {
                float2 v = up2(acc[p]);
                g_theta[(r0 + 2 * p + 0) * NGEN + m] = v.x;
                g_theta[(r0 + 2 * p + 1) * NGEN + m] = v.y;
            }
        }
    }
}

// ---------------- Kernel C: H via WHT, psi = exp(iH)e0 (Chebyshev), obs + head1 ----------------
__global__ void __launch_bounds__(64) k_expq(const float* __restrict__ Aoff,
                                             const float* __restrict__ Boff,
                                             const float* __restrict__ Ddiag,
                                             const float* __restrict__ Wv1,
                                             const float* __restrict__ bv1) {
    __shared__ float Gre[64 * 64];
    __shared__ float Gim[64 * 64];
    __shared__ float2 us[2][64];
    __shared__ float psr[64], psi_[64];
    __shared__ float sred[2];
    __shared__ float cf[CFMAX];
    __shared__ float qs[NOBS];

    int b = blockIdx.x;
    int x = threadIdx.x;
    const float* th = g_theta + b * NGEN;

    // gather phased thetas via precomputed table; accumulate sum(theta^2)
    float s2 = 0.f;
#pragma unroll 4
    for (int z = 0; z < 64; z++) {
        int e = g_idx[(z << 6) + x];
        float tv = th[e & 0xFFFF];
        if ((x | z) == 0) tv = 0.f;
        s2 = fmaf(tv, tv, s2);
        int pc = e >> 16;
        float sv = (pc & 2) ? -tv : tv;
        float re = (pc & 1) ? 0.f : sv;
        float im = (pc & 1) ? sv : 0.f;
        Gre[z * 64 + x] = re;
        Gim[z * 64 + x] = im;
    }
#pragma unroll
    for (int m = 16; m > 0; m >>= 1) s2 += __shfl_xor_sync(0xffffffffu, s2, m);
    if ((x & 31) == 0) sred[x >> 5] = s2;

    // 64-point WHT along z, per column x (thread-private -> no syncs)
#pragma unroll
    for (int st = 0; st < 6; st++) {
        int hsz = 1 << st;
        for (int zb = 0; zb < 64; zb += (hsz << 1)) {
            for (int k = 0; k < hsz; k++) {
                int i0 = (zb + k) * 64 + x, i1 = (zb + k + hsz) * 64 + x;
                float ar = Gre[i0], ai = Gim[i0];
                float br = Gre[i1], bi = Gim[i1];
                Gre[i0] = ar + br; Gim[i0] = ai + bi;
                Gre[i1] = ar - br; Gim[i1] = ai - bi;
            }
        }
    }
    __syncthreads();
    // H[i][j] = G[j*64+(i^j)] -> row x to registers (conflict-free)
    float Hr[64], Hi[64];
#pragma unroll
    for (int j = 0; j < 64; j++) {
        int gi = (j << 6) + (x ^ j);
        Hr[j] = Gre[gi];
        Hi[j] = Gim[gi];
    }

    // Chebyshev interval: a' = 1.35 * semicircle edge
    float ap = 2.7f * sqrtf(sred[0] + sred[1]);
    if (ap < 4.f) ap = 4.f;
    float inva = 1.f / ap;
    int K = (int)ceilf(ap + 6.f * cbrtf(ap) + 2.f);
    if (K > CFMAX - 20) K = CFMAX - 20;
    int mstart = K + 12; mstart += (mstart & 1);

    // Miller downward recurrence for J_k(ap) (redundant per thread; thread 0 stores)
    {
        float jkp1 = 0.f, jk = 1e-20f, sum = 0.f;
        for (int k = mstart; k >= 1; --k) {
            if (k < CFMAX && x == 0) cf[k] = jk;
            if ((k & 1) == 0) sum += 2.f * jk;
            float jkm1 = fmaf(2.f * (float)k * inva, jk, -jkp1);
            jkp1 = jk; jk = jkm1;
        }
        if (x == 0) cf[0] = jk;
        sum += jk;
        psr[0] = 1.f / sum;
    }
    __syncthreads();
    float invn = psr[0];
    __syncthreads();

    // psi = sum_k i^k (2-d_k0) J_k T_k(H/a') e0
    float tpr = (x == 0) ? 1.f : 0.f, tpi = 0.f;
    float tcr = Hr[0] * inva, tci = Hi[0] * inva;
    float accr = cf[0] * invn * tpr, acci = 0.f;
    {
        float g1 = 2.f * cf[1] * invn;
        accr = fmaf(-g1, tci, accr);
        acci = fmaf( g1, tcr, acci);
    }
    float twoinva = 2.f * inva;
    int buf = 0;
#pragma unroll 1
    for (int k = 2; k <= K; k++) {
        us[buf][x] = make_float2(tcr, tci);
        __syncthreads();
        float wr0 = 0.f, wi0 = 0.f, wr1 = 0.f, wi1 = 0.f;
        float wr2 = 0.f, wi2 = 0.f, wr3 = 0.f, wi3 = 0.f;
#pragma unroll
        for (int j = 0; j < 64; j += 4) {
            float2 u0 = us[buf][j];
            float2 u1 = us[buf][j + 1];
            float2 u2 = us[buf][j + 2];
            float2 u3 = us[buf][j + 3];
            wr0 = fmaf(Hr[j],     u0.x, wr0); wr0 = fmaf(-Hi[j],     u0.y, wr0);
            wi0 = fmaf(Hr[j],     u0.y, wi0); wi0 = fmaf( Hi[j],     u0.x, wi0);
            wr1 = fmaf(Hr[j + 1], u1.x, wr1); wr1 = fmaf(-Hi[j + 1], u1.y, wr1);
            wi1 = fmaf(Hr[j + 1], u1.y, wi1); wi1 = fmaf( Hi[j + 1], u1.x, wi1);
            wr2 = fmaf(Hr[j + 2], u2.x, wr2); wr2 = fmaf(-Hi[j + 2], u2.y, wr2);
            wi2 = fmaf(Hr[j + 2], u2.y, wi2); wi2 = fmaf( Hi[j + 2], u2.x, wi2);
            wr3 = fmaf(Hr[j + 3], u3.x, wr3); wr3 = fmaf(-Hi[j + 3], u3.y, wr3);
            wi3 = fmaf(Hr[j + 3], u3.y, wi3); wi3 = fmaf( Hi[j + 3], u3.x, wi3);
        }
        float wr = (wr0 + wr1) + (wr2 + wr3);
        float wi = (wi0 + wi1) + (wi2 + wi3);
        float tnr = fmaf(twoinva, wr, -tpr);
        float tni = fmaf(twoinva, wi, -tpi);
        tpr = tcr; tpi = tci; tcr = tnr; tci = tni;
        float g = 2.f * cf[k] * invn;
        int p = k & 3;
        float gr = (p == 0) ? g : ((p == 2) ? -g : 0.f);
        float gi = (p == 1) ? g : ((p == 3) ? -g : 0.f);
        accr = fmaf(gr, tcr, accr); accr = fmaf(-gi, tci, accr);
        acci = fmaf(gr, tci, acci); acci = fmaf( gi, tcr, acci);
        buf ^= 1;
    }
    __syncthreads();
    psr[x] = accr; psi_[x] = acci;
    __syncthreads();

    // observables -> qs[15]
    if (x < NOBS) {
        int a = PAIR_A[x], bw = PAIR_B[x];
        int pa = 5 - a, pb = 5 - bw;
        float dsum[4] = {0, 0, 0, 0};
        float orr[6] = {0, 0, 0, 0, 0, 0}, oii[6] = {0, 0, 0, 0, 0, 0};
        for (int r = 0; r < 16; r++) {
            int n0 = 0, rr = r;
#pragma unroll
            for (int p = 0; p < 6; p++) {
                if (p != pa && p != pb) { n0 |= (rr & 1) << p; rr >>= 1; }
            }
            float prk[4], pik[4];
#pragma unroll
            for (int k = 0; k < 4; k++) {
                int n = n0 | (((k >> 1) & 1) << pa) | ((k & 1) << pb);
                prk[k] = psr[n]; pik[k] = psi_[n];
            }
#pragma unroll
            for (int k = 0; k < 4; k++) dsum[k] += prk[k] * prk[k] + pik[k] * pik[k];
            int c = 0;
#pragma unroll
            for (int l = 1; l < 4; l++)
                for (int k = 0; k < l; k++) {
                    orr[c] += prk[k] * prk[l] + pik[k] * pik[l];
                    oii[c] += pik[k] * prk[l] - prk[k] * pik[l];
                    c++;
                }
        }
        float q = 0.f;
#pragma unroll
        for (int dd = 0; dd < 3; dd++) q += 2.f * Ddiag[x * 4 + dd + 1] * dsum[dd];
#pragma unroll
        for (int c = 0; c < 6; c++) {
            float A = Aoff[x * 6 + c], B = Boff[x * 6 + c];
            q += 2.f * (orr[c] * A - oii[c] * B);
        }
        qs[x] = q;
    }
    __syncthreads();

    // fused head1: hh = silu(q @ Wv1 + bv1), 4 hidden cols per thread
    {
        int c0 = x * 4;
        float h0 = bv1[c0], h1 = bv1[c0 + 1], h2 = bv1[c0 + 2], h3 = bv1[c0 + 3];
#pragma unroll
        for (int j = 0; j < NOBS; j++) {
            float qv = qs[j];
            const float* wr = Wv1 + j * HID + c0;
            h0 = fmaf(qv, wr[0], h0);
            h1 = fmaf(qv, wr[1], h1);
            h2 = fmaf(qv, wr[2], h2);
            h3 = fmaf(qv, wr[3], h3);
        }
        float* o = g_hh + b * HID + c0;
        o[0] = h0 / (1.f + expf(-h0));
        o[1] = h1 / (1.f + expf(-h1));
        o[2] = h2 / (1.f + expf(-h2));
        o[3] = h3 / (1.f + expf(-h3));
    }
}

// ---------------- Kernel D: out = hh @ Wv2 + bv2 (f32x2), 4 rows/block, 512 thr ----------------
__global__ void k_head2(const float* __restrict__ Wv2, const float* __restrict__ bv2,
                        float* __restrict__ out) {
    __shared__ float hsT4[HID][4];   // transposed 4-row tile (16B stride)
    int r0 = blockIdx.x * 4, t = threadIdx.x;
    for (int i = t; i < 4 * HID; i += 512) {
        int j = i & 255, r = i >> 8;
        hsT4[j][r] = g_hh[(r0 + r) * HID + j];
    }
    __syncthreads();
    int o = t;
    float bo = bv2[o];
    ull a01 = pk2(bo, bo), a23 = pk2(bo, bo);
    ull b01 = pk2(0.f, 0.f), b23 = pk2(0.f, 0.f);
#pragma unroll 4
    for (int j = 0; j < HID; j += 2) {
        float w0 = Wv2[j * OUT_DIM + o];
        float w1 = Wv2[(j + 1) * OUT_DIM + o];
        ull wd0 = pk2(w0, w0), wd1 = pk2(w1, w1);
        longlong2 h0 = *(const longlong2*)&hsT4[j][0];
        longlong2 h1 = *(const longlong2*)&hsT4[j + 1][0];
        fma2(a01, (ull)h0.x, wd0); fma2(a23, (ull)h0.y, wd0);
        fma2(b01, (ull)h1.x, wd1); fma2(b23, (ull)h1.y, wd1);
    }
    float2 v01 = up2(a01), v23 = up2(a23), w01 = up2(b01), w23 = up2(b23);
    out[(r0 + 0) * OUT_DIM + o] = v01.x + w01.x;
    out[(r0 + 1) * OUT_DIM + o] = v01.y + w01.y;
    out[(r0 + 2) * OUT_DIM + o] = v23.x + w23.x;
    out[(r0 + 3) * OUT_DIM + o] = v23.y + w23.y;
}

extern "C" void kernel_launch(void* const* d_in, const int* in_sizes, int n_in,
                              void* d_out, int out_size) {
    const float* x    = (const float*)d_in[0];
    const float* W1   = (const float*)d_in[1];
    const float* b1   = (const float*)d_in[2];
    const float* W2   = (const float*)d_in[3];
    const float* b2   = (const float*)d_in[4];
    const float* Aoff = (const float*)d_in[5];
    const float* Boff = (const float*)d_in[6];
    const float* Dd   = (const float*)d_in[7];
    const float* Wv1  = (const float*)d_in[8];
    const float* bv1  = (const float*)d_in[9];
    const float* Wv2  = (const float*)d_in[10];
    const float* bv2  = (const float*)d_in[11];
    // d_in[12] = pauli basis: unused (Pauli structure computed analytically)
    float* out = (float*)d_out;

    k_init_idx<<<16, 256>>>();
    k_mlp1<<<BATCH / 8, 256>>>(x, W1, b1);
    dim3 g2(BATCH / 16, 4);
    k_mlp2<<<g2, 256>>>(W2, b2);
    k_expq<<<BATCH, 64>>>(Aoff, Boff, Dd, Wv1, bv1);
    k_head2<<<BATCH / 4, 512>>>(Wv2, bv2, out);
}

// round 6
// speedup vs baseline: 3.1136x; 1.0011x over previous
#include <cuda_runtime.h>
#include <math.h>

#define BATCH   512
#define IN_DIM  768
#define HID     256
#define NGEN    4095
#define NOBS    15
#define OUT_DIM 512
#define DIM     64
#define CFMAX   256

typedef unsigned long long ull;

// -------- scratch (static device globals; no runtime allocation) --------
__device__ float g_h[BATCH * HID];        // hidden of enc MLP
__device__ float g_theta[BATCH * NGEN];   // SU(64) angles
__device__ float g_hh[BATCH * HID];       // hidden of vel head (head1 fused in expq)
__device__ int   g_idx[DIM * DIM];        // (m-1) | (phase<<16) Pauli gather table

__device__ const int PAIR_A[15] = {0,0,0,0,0,1,1,1,1,2,2,2,3,3,4};
__device__ const int PAIR_B[15] = {1,2,3,4,5,2,3,4,5,3,4,5,4,5,5};

// ---- f32x2 helpers ----
__device__ __forceinline__ ull pk2(float lo, float hi) {
    ull r; asm("mov.b64 %0, {%1,%2};" : "=l"(r) : "f"(lo), "f"(hi)); return r;
}
__device__ __forceinline__ void fma2(ull& d, ull a, ull b) {
    asm("fma.rn.f32x2 %0, %1, %2, %0;" : "+l"(d) : "l"(a), "l"(b));
}
__device__ __forceinline__ float2 up2(ull v) {
    float2 f; asm("mov.b64 {%0,%1}, %2;" : "=f"(f.x), "=f"(f.y) : "l"(v)); return f;
}

// ---------------- Kernel A: h = silu(x @ W1 + b1), 8 rows/block (+ idx table init) ----------------
__global__ void k_mlp1(const float* __restrict__ x, const float* __restrict__ W1,
                       const float* __restrict__ b1) {
    __shared__ float xs[8][IN_DIM];
    int r0 = blockIdx.x * 8;
    int t  = threadIdx.x;
    // fold: Pauli gather index table (input-independent, rewritten every call)
    {
        int gi = blockIdx.x * 256 + t;
        if (gi < DIM * DIM) {
            int xx = gi & 63, zz = gi >> 6;
            int m = 0;
#pragma unroll
            for (int p = 0; p < 6; p++) {
                int l = ((xx >> p) & 1) + 3 * ((zz >> p) & 1) - 2 * (((xx & zz) >> p) & 1);
                m += l << (2 * p);
            }
            int pc = __popc(xx & zz) & 3;
            g_idx[gi] = (gi == 0) ? 0 : ((m - 1) | (pc << 16));
        }
    }
    for (int i = t; i < 8 * IN_DIM; i += 256) {
        int r = i / IN_DIM, c = i % IN_DIM;
        xs[r][c] = x[(r0 + r) * IN_DIM + c];
    }
    __syncthreads();
    float acc[8];
    float bb = b1[t];
#pragma unroll
    for (int r = 0; r < 8; r++) acc[r] = bb;
#pragma unroll 2
    for (int i = 0; i < IN_DIM; i += 4) {
        float w0 = W1[(i + 0) * HID + t];
        float w1 = W1[(i + 1) * HID + t];
        float w2 = W1[(i + 2) * HID + t];
        float w3 = W1[(i + 3) * HID + t];
#pragma unroll
        for (int r = 0; r < 8; r++) {
            float4 xv = *(const float4*)&xs[r][i];
            acc[r] = fmaf(xv.x, w0, acc[r]);
            acc[r] = fmaf(xv.y, w1, acc[r]);
            acc[r] = fmaf(xv.z, w2, acc[r]);
            acc[r] = fmaf(xv.w, w3, acc[r]);
        }
    }
#pragma unroll
    for (int r = 0; r < 8; r++) {
        float a = acc[r];
        g_h[(r0 + r) * HID + t] = a / (1.f + expf(-a));
    }
}

// ---------------- Kernel B: theta = h @ W2 + b2 (f32x2), 16 rows x 1024-col ----------------
#define PADR 20
__global__ void k_mlp2(const float* __restrict__ W2, const float* __restrict__ b2) {
    __shared__ float hsT[HID][PADR];
    int r0    = blockIdx.x * 16;
    int mbase = blockIdx.y * 1024;
    int t     = threadIdx.x;
    for (int i = t; i < 16 * HID; i += 256) {
        int j = i & 255, r = i >> 8;
        hsT[j][r] = g_h[(r0 + r) * HID + j];
    }
    __syncthreads();
    for (int k = 0; k < 4; k++) {
        int m = mbase + t + 256 * k;
        if (m < NGEN) {
            float bb = b2[m];
            ull acc[8];
#pragma unroll
            for (int p = 0; p < 8; p++) acc[p] = pk2(0.f, 0.f);
            acc[0] = pk2(bb, bb); acc[4] = pk2(bb, bb);
#pragma unroll 2
            for (int j = 0; j < HID; j += 2) {
                float w0 = W2[(j + 0) * NGEN + m];
                float w1 = W2[(j + 1) * NGEN + m];
                ull wd0 = pk2(w0, w0), wd1 = pk2(w1, w1);
#pragma unroll
                for (int p = 0; p < 4; p++) {
                    longlong2 h0 = *(const longlong2*)&hsT[j][4 * p];
                    longlong2 h1 = *(const longlong2*)&hsT[j + 1][4 * p];
                    fma2(acc[2 * p],     (ull)h0.x, wd0);
                    fma2(acc[2 * p + 1], (ull)h0.y, wd0);
                    fma2(acc[2 * p],     (ull)h1.x, wd1);
                    fma2(acc[2 * p + 1], (ull)h1.y, wd1);
                }
            }
            // acc[0],acc[4] carried bias for rows 0,1 and 8,9; others need it too
            // (bias placement: rows 0..15 = pairs p: rows 2p,2p+1). Add bias to rest:
#pragma unroll
            for (int p = 0; p < 8; p++) {
                float2 v = up2(acc[p]);
                float add = (p == 0 || p == 4) ? 0.f : bb;
                g_theta[(r0 + 2 * p + 0) * NGEN + m] = v.x + add;
                g_theta[(r0 + 2 * p + 1) * NGEN + m] = v.y + add;
            }
        }
    }
}

// ---------------- Kernel C: register WHT, psi = exp(iH)e0 (Chebyshev), obs + head1 ----------------
// 128 threads per batch element: WHT phase t=(x,h)=(t&63,t>>6); matvec phase t=(row,par)=(t>>1,t&1)
__global__ void __launch_bounds__(128) k_expq(const float* __restrict__ Aoff,
                                              const float* __restrict__ Boff,
                                              const float* __restrict__ Ddiag,
                                              const float* __restrict__ Wv1,
                                              const float* __restrict__ bv1) {
    __shared__ float Gre[64 * 64];   // stage-4 partials: [32h+zi][x]
    __shared__ float Gim[64 * 64];
    __shared__ float2 us[2][64];
    __shared__ float psr[64], psi_[64];
    __shared__ float sred[4];
    __shared__ float cf[CFMAX];
    __shared__ float qs[NOBS];
    __shared__ float invn_s;

    int b = blockIdx.x;
    int t = threadIdx.x;
    const float* th = g_theta + b * NGEN;

    // ---- gather half-column into registers + sum(theta^2) ----
    int x = t & 63, h = t >> 6;
    float vr[32], vi[32];
    float s2 = 0.f;
#pragma unroll
    for (int zi = 0; zi < 32; zi++) {
        int z = 32 * h + zi;
        int e = g_idx[(z << 6) + x];
        float tv = th[e & 0xFFFF];
        if ((x | z) == 0) tv = 0.f;
        s2 = fmaf(tv, tv, s2);
        int pc = e >> 16;
        float sv = (pc & 2) ? -tv : tv;
        vr[zi] = (pc & 1) ? 0.f : sv;
        vi[zi] = (pc & 1) ? sv : 0.f;
    }
#pragma unroll
    for (int m = 16; m > 0; m >>= 1) s2 += __shfl_xor_sync(0xffffffffu, s2, m);
    if ((t & 31) == 0) sred[t >> 5] = s2;

    // ---- WHT stages 0..4 entirely in registers ----
#pragma unroll
    for (int st = 0; st < 5; st++) {
        int hsz = 1 << st;
#pragma unroll
        for (int zb = 0; zb < 32; zb += 2 * hsz) {
#pragma unroll
            for (int k = 0; k < hsz; k++) {
                int i0 = zb + k, i1 = zb + k + hsz;
                float ar = vr[i0], br = vr[i1];
                vr[i0] = ar + br; vr[i1] = ar - br;
                float ai = vi[i0], bi = vi[i1];
                vi[i0] = ai + bi; vi[i1] = ai - bi;
            }
        }
    }
    // store partials (conflict-free: x consecutive across warp)
#pragma unroll
    for (int zi = 0; zi < 32; zi++) {
        Gre[(32 * h + zi) * 64 + x] = vr[zi];
        Gim[(32 * h + zi) * 64 + x] = vi[zi];
    }
    __syncthreads();

    // ---- load H row with stage-5 fold: H[r][j] = P0[j&31][r^j] +- P1[j&31][r^j] ----
    int r = t >> 1, p = t & 1;
    float Hr[32], Hi[32];
#pragma unroll
    for (int jj = 0; jj < 32; jj++) {
        int j = 2 * jj + p;
        int jl = j & 31, xr = r ^ j;
        float ar = Gre[jl * 64 + xr],        ai = Gim[jl * 64 + xr];
        float br = Gre[(32 + jl) * 64 + xr], bi = Gim[(32 + jl) * 64 + xr];
        if (j & 32) { Hr[jj] = ar - br; Hi[jj] = ai - bi; }
        else        { Hr[jj] = ar + br; Hi[jj] = ai + bi; }
    }

    // ---- Chebyshev interval ----
    float ap = 2.7f * sqrtf((sred[0] + sred[1]) + (sred[2] + sred[3]));
    if (ap < 4.f) ap = 4.f;
    float inva = 1.f / ap;
    int K = (int)ceilf(ap + 6.f * cbrtf(ap) + 2.f);
    if (K > CFMAX - 20) K = CFMAX - 20;
    int mstart = K + 12; mstart += (mstart & 1);

    // Miller downward recurrence (redundant; thread 0 stores)
    {
        float jkp1 = 0.f, jk = 1e-20f, sum = 0.f;
        for (int k = mstart; k >= 1; --k) {
            if (k < CFMAX && t == 0) cf[k] = jk;
            if ((k & 1) == 0) sum += 2.f * jk;
            float jkm1 = fmaf(2.f * (float)k * inva, jk, -jkp1);
            jkp1 = jk; jk = jkm1;
        }
        if (t == 0) { cf[0] = jk; invn_s = 1.f / (sum + jk); }
    }
    __syncthreads();
    float invn = invn_s;

    // ---- psi = sum_k i^k (2-d_k0) J_k T_k(H/a') e0, 2 threads per row ----
    float tpr = (r == 0) ? 1.f : 0.f, tpi = 0.f;    // T0
    float t1r = (p == 0) ? Hr[0] * inva : 0.f;       // T1 = (H/a') e0 : column j=0 owned by p=0
    float t1i = (p == 0) ? Hi[0] * inva : 0.f;
    t1r += __shfl_xor_sync(0xffffffffu, t1r, 1);
    t1i += __shfl_xor_sync(0xffffffffu, t1i, 1);
    float tcr = t1r, tci = t1i;
    float accr = cf[0] * invn * tpr, acci = 0.f;
    {
        float g1 = 2.f * cf[1] * invn;
        accr = fmaf(-g1, tci, accr);
        acci = fmaf( g1, tcr, acci);
    }
    float twoinva = 2.f * inva;
    int buf = 0;
#pragma unroll 1
    for (int k = 2; k <= K; k++) {
        if (p == 0) us[buf][r] = make_float2(tcr, tci);
        __syncthreads();
        float wr0 = 0.f, wi0 = 0.f, wr1 = 0.f, wi1 = 0.f;
        float wr2 = 0.f, wi2 = 0.f, wr3 = 0.f, wi3 = 0.f;
#pragma unroll
        for (int jj = 0; jj < 32; jj += 4) {
            float2 u0 = us[buf][2 * jj + p];
            float2 u1 = us[buf][2 * (jj + 1) + p];
            float2 u2 = us[buf][2 * (jj + 2) + p];
            float2 u3 = us[buf][2 * (jj + 3) + p];
            wr0 = fmaf(Hr[jj],     u0.x, wr0); wr0 = fmaf(-Hi[jj],     u0.y, wr0);
            wi0 = fmaf(Hr[jj],     u0.y, wi0); wi0 = fmaf( Hi[jj],     u0.x, wi0);
            wr1 = fmaf(Hr[jj + 1], u1.x, wr1); wr1 = fmaf(-Hi[jj + 1], u1.y, wr1);
            wi1 = fmaf(Hr[jj + 1], u1.y, wi1); wi1 = fmaf( Hi[jj + 1], u1.x, wi1);
            wr2 = fmaf(Hr[jj + 2], u2.x, wr2); wr2 = fmaf(-Hi[jj + 2], u2.y, wr2);
            wi2 = fmaf(Hr[jj + 2], u2.y, wi2); wi2 = fmaf( Hi[jj + 2], u2.x, wi2);
            wr3 = fmaf(Hr[jj + 3], u3.x, wr3); wr3 = fmaf(-Hi[jj + 3], u3.y, wr3);
            wi3 = fmaf(Hr[jj + 3], u3.y, wi3); wi3 = fmaf( Hi[jj + 3], u3.x, wi3);
        }
        float wr = (wr0 + wr1) + (wr2 + wr3);
        float wi = (wi0 + wi1) + (wi2 + wi3);
        wr += __shfl_xor_sync(0xffffffffu, wr, 1);   // combine column parities
        wi += __shfl_xor_sync(0xffffffffu, wi, 1);
        float tnr = fmaf(twoinva, wr, -tpr);
        float tni = fmaf(twoinva, wi, -tpi);
        tpr = tcr; tpi = tci; tcr = tnr; tci = tni;
        float g = 2.f * cf[k] * invn;
        int pp = k & 3;
        float gr = (pp == 0) ? g : ((pp == 2) ? -g : 0.f);
        float gi = (pp == 1) ? g : ((pp == 3) ? -g : 0.f);
        accr = fmaf(gr, tcr, accr); accr = fmaf(-gi, tci, accr);
        acci = fmaf(gr, tci, acci); acci = fmaf( gi, tcr, acci);
        buf ^= 1;
    }
    if (p == 0) { psr[r] = accr; psi_[r] = acci; }
    __syncthreads();

    // ---- observables -> qs[15] (threads 0..14) ----
    if (t < NOBS) {
        int a = PAIR_A[t], bw = PAIR_B[t];
        int pa = 5 - a, pb = 5 - bw;
        float dsum[4] = {0, 0, 0, 0};
        float orr[6] = {0, 0, 0, 0, 0, 0}, oii[6] = {0, 0, 0, 0, 0, 0};
        for (int rr_ = 0; rr_ < 16; rr_++) {
            int n0 = 0, rr = rr_;
#pragma unroll
            for (int pq = 0; pq < 6; pq++) {
                if (pq != pa && pq != pb) { n0 |= (rr & 1) << pq; rr >>= 1; }
            }
            float prk[4], pik[4];
#pragma unroll
            for (int k = 0; k < 4; k++) {
                int n = n0 | (((k >> 1) & 1) << pa) | ((k & 1) << pb);
                prk[k] = psr[n]; pik[k] = psi_[n];
            }
#pragma unroll
            for (int k = 0; k < 4; k++) dsum[k] += prk[k] * prk[k] + pik[k] * pik[k];
            int c = 0;
#pragma unroll
            for (int l = 1; l < 4; l++)
                for (int k = 0; k < l; k++) {
                    orr[c] += prk[k] * prk[l] + pik[k] * pik[l];
                    oii[c] += pik[k] * prk[l] - prk[k] * pik[l];
                    c++;
                }
        }
        float q = 0.f;
#pragma unroll
        for (int dd = 0; dd < 3; dd++) q += 2.f * Ddiag[t * 4 + dd + 1] * dsum[dd];
#pragma unroll
        for (int c = 0; c < 6; c++) {
            float A = Aoff[t * 6 + c], B = Boff[t * 6 + c];
            q += 2.f * (orr[c] * A - oii[c] * B);
        }
        qs[t] = q;
    }
    __syncthreads();

    // ---- fused head1: hh = silu(q @ Wv1 + bv1), 2 hidden cols per thread ----
    {
        int c0 = t * 2;
        float h0 = bv1[c0], h1 = bv1[c0 + 1];
#pragma unroll
        for (int j = 0; j < NOBS; j++) {
            float qv = qs[j];
            h0 = fmaf(qv, Wv1[j * HID + c0], h0);
            h1 = fmaf(qv, Wv1[j * HID + c0 + 1], h1);
        }
        float* o = g_hh + b * HID + c0;
        o[0] = h0 / (1.f + expf(-h0));
        o[1] = h1 / (1.f + expf(-h1));
    }
}

// ---------------- Kernel D: out = hh @ Wv2 + bv2 (f32x2), 4 rows/block, 512 thr ----------------
__global__ void k_head2(const float* __restrict__ Wv2, const float* __restrict__ bv2,
                        float* __restrict__ out) {
    __shared__ float hsT4[HID][4];
    int r0 = blockIdx.x * 4, t = threadIdx.x;
    for (int i = t; i < 4 * HID; i += 512) {
        int j = i & 255, r = i >> 8;
        hsT4[j][r] = g_hh[(r0 + r) * HID + j];
    }
    __syncthreads();
    int o = t;
    float bo = bv2[o];
    ull a01 = pk2(bo, bo), a23 = pk2(bo, bo);
    ull b01 = pk2(0.f, 0.f), b23 = pk2(0.f, 0.f);
#pragma unroll 4
    for (int j = 0; j < HID; j += 2) {
        float w0 = Wv2[j * OUT_DIM + o];
        float w1 = Wv2[(j + 1) * OUT_DIM + o];
        ull wd0 = pk2(w0, w0), wd1 = pk2(w1, w1);
        longlong2 h0 = *(const longlong2*)&hsT4[j][0];
        longlong2 h1 = *(const longlong2*)&hsT4[j + 1][0];
        fma2(a01, (ull)h0.x, wd0); fma2(a23, (ull)h0.y, wd0);
        fma2(b01, (ull)h1.x, wd1); fma2(b23, (ull)h1.y, wd1);
    }
    float2 v01 = up2(a01), v23 = up2(a23), w01 = up2(b01), w23 = up2(b23);
    out[(r0 + 0) * OUT_DIM + o] = v01.x + w01.x;
    out[(r0 + 1) * OUT_DIM + o] = v01.y + w01.y;
    out[(r0 + 2) * OUT_DIM + o] = v23.x + w23.x;
    out[(r0 + 3) * OUT_DIM + o] = v23.y + w23.y;
}

extern "C" void kernel_launch(void* const* d_in, const int* in_sizes, int n_in,
                              void* d_out, int out_size) {
    const float* x    = (const float*)d_in[0];
    const float* W1   = (const float*)d_in[1];
    const float* b1   = (const float*)d_in[2];
    const float* W2   = (const float*)d_in[3];
    const float* b2   = (const float*)d_in[4];
    const float* Aoff = (const float*)d_in[5];
    const float* Boff = (const float*)d_in[6];
    const float* Dd   = (const float*)d_in[7];
    const float* Wv1  = (const float*)d_in[8];
    const float* bv1  = (const float*)d_in[9];
    const float* Wv2  = (const float*)d_in[10];
    const float* bv2  = (const float*)d_in[11];
    // d_in[12] = pauli basis: unused (Pauli structure computed analytically)
    float* out = (float*)d_out;

    k_mlp1<<<BATCH / 8, 256>>>(x, W1, b1);
    dim3 g2(BATCH / 16, 4);
    k_mlp2<<<g2, 256>>>(W2, b2);
    k_expq<<<BATCH, 128>>>(Aoff, Boff, Dd, Wv1, bv1);
    k_head2<<<BATCH / 4, 512>>>(Wv2, bv2, out);
}

// round 11
// speedup vs baseline: 3.1786x; 1.0209x over previous
#include <cuda_runtime.h>
#include <math.h>

#define BATCH   512
#define IN_DIM  768
#define HID     256
#define NGEN    4095
#define NOBS    15
#define OUT_DIM 512
#define DIM     64
#define CFMAX   256

typedef unsigned long long ull;

// -------- scratch (static device globals; no runtime allocation) --------
__device__ float g_h[BATCH * HID];        // hidden of enc MLP
__device__ float g_theta[BATCH * NGEN];   // SU(64) angles
__device__ float g_hh[BATCH * HID];       // hidden of vel head (head1 fused in expq)
__device__ int   g_idx[DIM * DIM];        // (m-1) | (phase<<16) Pauli gather table

__device__ const int PAIR_A[15] = {0,0,0,0,0,1,1,1,1,2,2,2,3,3,4};
__device__ const int PAIR_B[15] = {1,2,3,4,5,2,3,4,5,3,4,5,4,5,5};

// ---- f32x2 helpers ----
__device__ __forceinline__ ull pk2(float lo, float hi) {
    ull r; asm("mov.b64 %0, {%1,%2};" : "=l"(r) : "f"(lo), "f"(hi)); return r;
}
__device__ __forceinline__ void fma2(ull& d, ull a, ull b) {
    asm("fma.rn.f32x2 %0, %1, %2, %0;" : "+l"(d) : "l"(a), "l"(b));
}
__device__ __forceinline__ float2 up2(ull v) {
    float2 f; asm("mov.b64 {%0,%1}, %2;" : "=f"(f.x), "=f"(f.y) : "l"(v)); return f;
}

// ---------------- Kernel A: h = silu(x @ W1 + b1), 8 rows/block (+ idx table init) ----------------
__global__ void k_mlp1(const float* __restrict__ x, const float* __restrict__ W1,
                       const float* __restrict__ b1) {
    __shared__ float xs[8][IN_DIM];
    int r0 = blockIdx.x * 8;
    int t  = threadIdx.x;
    // fold: Pauli gather index table (input-independent, rewritten every call)
    {
        int gi = blockIdx.x * 256 + t;
        if (gi < DIM * DIM) {
            int xx = gi & 63, zz = gi >> 6;
            int m = 0;
#pragma unroll
            for (int p = 0; p < 6; p++) {
                int l = ((xx >> p) & 1) + 3 * ((zz >> p) & 1) - 2 * (((xx & zz) >> p) & 1);
                m += l << (2 * p);
            }
            int pc = __popc(xx & zz) & 3;
            g_idx[gi] = (gi == 0) ? 0 : ((m - 1) | (pc << 16));
        }
    }
    for (int i = t; i < 8 * IN_DIM; i += 256) {
        int r = i / IN_DIM, c = i % IN_DIM;
        xs[r][c] = x[(r0 + r) * IN_DIM + c];
    }
    __syncthreads();
    float acc[8];
    float bb = b1[t];
#pragma unroll
    for (int r = 0; r < 8; r++) acc[r] = bb;
#pragma unroll 2
    for (int i = 0; i < IN_DIM; i += 4) {
        float w0 = W1[(i + 0) * HID + t];
        float w1 = W1[(i + 1) * HID + t];
        float w2 = W1[(i + 2) * HID + t];
        float w3 = W1[(i + 3) * HID + t];
#pragma unroll
        for (int r = 0; r < 8; r++) {
            float4 xv = *(const float4*)&xs[r][i];
            acc[r] = fmaf(xv.x, w0, acc[r]);
            acc[r] = fmaf(xv.y, w1, acc[r]);
            acc[r] = fmaf(xv.z, w2, acc[r]);
            acc[r] = fmaf(xv.w, w3, acc[r]);
        }
    }
#pragma unroll
    for (int r = 0; r < 8; r++) {
        float a = acc[r];
        g_h[(r0 + r) * HID + t] = a / (1.f + expf(-a));
    }
}

// ---------------- Kernel B: theta = h @ W2 + b2 (f32x2, 16x4 register C-tile) ----------------
// grid (32, 4), 256 threads. Thread t owns cols {m, m+256, m+512, m+768}, all 16 rows.
__global__ void k_mlp2(const float* __restrict__ W2, const float* __restrict__ b2) {
    __shared__ float hsT[HID][20];    // transposed tile, 80B row stride (16B-aligned)
    int r0    = blockIdx.x * 16;
    int mbase = blockIdx.y * 1024;
    int t     = threadIdx.x;
    for (int i = t; i < 16 * HID; i += 256) {
        int j = i & 255, r = i >> 8;
        hsT[j][r] = g_h[(r0 + r) * HID + j];   // coalesced LDG; 4-way LDS store conflict (one-time)
    }
    __syncthreads();
    int m = mbase + t;
    ull acc[4][8];
#pragma unroll
    for (int k = 0; k < 4; k++)
#pragma unroll
        for (int p = 0; p < 8; p++) acc[k][p] = pk2(0.f, 0.f);
#pragma unroll 2
    for (int j = 0; j < HID; j++) {
        ull wd[4];
#pragma unroll
        for (int k = 0; k < 4; k++) {
            int mm = m + 256 * k; if (mm > NGEN - 1) mm = NGEN - 1;
            float w = W2[j * NGEN + mm];
            wd[k] = pk2(w, w);
        }
#pragma unroll
        for (int p = 0; p < 4; p++) {
            longlong2 hp = *(const longlong2*)&hsT[j][4 * p];   // rows 4p..4p+3 (broadcast)
#pragma unroll
            for (int k = 0; k < 4; k++) {
                fma2(acc[k][2 * p],     (ull)hp.x, wd[k]);
                fma2(acc[k][2 * p + 1], (ull)hp.y, wd[k]);
            }
        }
    }
#pragma unroll
    for (int k = 0; k < 4; k++) {
        int mm = m + 256 * k;
        if (mm < NGEN) {
            float bb = b2[mm];
#pragma unroll
            for (int p = 0; p < 8; p++) {
                float2 v = up2(acc[k][p]);
                g_theta[(r0 + 2 * p + 0) * NGEN + mm] = v.x + bb;
                g_theta[(r0 + 2 * p + 1) * NGEN + mm] = v.y + bb;
            }
        }
    }
}

// ---------------- Kernel C: register WHT, psi = exp(iH)e0 (Chebyshev), obs + head1 ----------------
// 128 threads per batch element: WHT phase t=(x,h)=(t&63,t>>6); matvec phase t=(row,par)=(t>>1,t&1)
__global__ void __launch_bounds__(128) k_expq(const float* __restrict__ Aoff,
                                              const float* __restrict__ Boff,
                                              const float* __restrict__ Ddiag,
                                              const float* __restrict__ Wv1,
                                              const float* __restrict__ bv1) {
    __shared__ float Gre[64 * 64];   // stage-4 partials: [32h+zi][x]
    __shared__ float Gim[64 * 64];
    __shared__ float2 us[2][64];
    __shared__ float psr[64], psi_[64];
    __shared__ float sred[4];
    __shared__ float cf[CFMAX];
    __shared__ float qs[NOBS];
    __shared__ float invn_s;

    int b = blockIdx.x;
    int t = threadIdx.x;
    const float* th = g_theta + b * NGEN;

    // ---- gather half-column into registers + sum(theta^2) ----
    int x = t & 63, h = t >> 6;
    float vr[32], vi[32];
    float s2 = 0.f;
#pragma unroll
    for (int zi = 0; zi < 32; zi++) {
        int z = 32 * h + zi;
        int e = g_idx[(z << 6) + x];
        float tv = th[e & 0xFFFF];
        if ((x | z) == 0) tv = 0.f;
        s2 = fmaf(tv, tv, s2);
        int pc = e >> 16;
        float sv = (pc & 2) ? -tv : tv;
        vr[zi] = (pc & 1) ? 0.f : sv;
        vi[zi] = (pc & 1) ? sv : 0.f;
    }
#pragma unroll
    for (int m = 16; m > 0; m >>= 1) s2 += __shfl_xor_sync(0xffffffffu, s2, m);
    if ((t & 31) == 0) sred[t >> 5] = s2;

    // ---- WHT stages 0..4 entirely in registers ----
#pragma unroll
    for (int st = 0; st < 5; st++) {
        int hsz = 1 << st;
#pragma unroll
        for (int zb = 0; zb < 32; zb += 2 * hsz) {
#pragma unroll
            for (int k = 0; k < hsz; k++) {
                int i0 = zb + k, i1 = zb + k + hsz;
                float ar = vr[i0], br = vr[i1];
                vr[i0] = ar + br; vr[i1] = ar - br;
                float ai = vi[i0], bi = vi[i1];
                vi[i0] = ai + bi; vi[i1] = ai - bi;
            }
        }
    }
#pragma unroll
    for (int zi = 0; zi < 32; zi++) {
        Gre[(32 * h + zi) * 64 + x] = vr[zi];
        Gim[(32 * h + zi) * 64 + x] = vi[zi];
    }
    __syncthreads();

    // ---- load H row with stage-5 fold: H[r][j] = P0[j&31][r^j] +- P1[j&31][r^j] ----
    int r = t >> 1, p = t & 1;
    float Hr[32], Hi[32];
#pragma unroll
    for (int jj = 0; jj < 32; jj++) {
        int j = 2 * jj + p;
        int jl = j & 31, xr = r ^ j;
        float ar = Gre[jl * 64 + xr],        ai = Gim[jl * 64 + xr];
        float br = Gre[(32 + jl) * 64 + xr], bi = Gim[(32 + jl) * 64 + xr];
        if (j & 32) { Hr[jj] = ar - br; Hi[jj] = ai - bi; }
        else        { Hr[jj] = ar + br; Hi[jj] = ai + bi; }
    }

    // ---- Chebyshev interval ----
    float ap = 2.7f * sqrtf((sred[0] + sred[1]) + (sred[2] + sred[3]));
    if (ap < 4.f) ap = 4.f;
    float inva = 1.f / ap;
    int K = (int)ceilf(ap + 6.f * cbrtf(ap) + 2.f);
    if (K > CFMAX - 20) K = CFMAX - 20;
    int mstart = K + 12; mstart += (mstart & 1);

    // Miller downward recurrence (redundant; thread 0 stores)
    {
        float jkp1 = 0.f, jk = 1e-20f, sum = 0.f;
        for (int k = mstart; k >= 1; --k) {
            if (k < CFMAX && t == 0) cf[k] = jk;
            if ((k & 1) == 0) sum += 2.f * jk;
            float jkm1 = fmaf(2.f * (float)k * inva, jk, -jkp1);
            jkp1 = jk; jk = jkm1;
        }
        if (t == 0) { cf[0] = jk; invn_s = 1.f / (sum + jk); }
    }
    __syncthreads();
    float invn = invn_s;

    // ---- psi = sum_k i^k (2-d_k0) J_k T_k(H/a') e0, 2 threads per row ----
    float tpr = (r == 0) ? 1.f : 0.f, tpi = 0.f;
    float t1r = (p == 0) ? Hr[0] * inva : 0.f;
    float t1i = (p == 0) ? Hi[0] * inva : 0.f;
    t1r += __shfl_xor_sync(0xffffffffu, t1r, 1);
    t1i += __shfl_xor_sync(0xffffffffu, t1i, 1);
    float tcr = t1r, tci = t1i;
    float accr = cf[0] * invn * tpr, acci = 0.f;
    {
        float g1 = 2.f * cf[1] * invn;
        accr = fmaf(-g1, tci, accr);
        acci = fmaf( g1, tcr, acci);
    }
    float twoinva = 2.f * inva;
    int buf = 0;
#pragma unroll 1
    for (int k = 2; k <= K; k++) {
        if (p == 0) us[buf][r] = make_float2(tcr, tci);
        __syncthreads();
        float wr0 = 0.f, wi0 = 0.f, wr1 = 0.f, wi1 = 0.f;
        float wr2 = 0.f, wi2 = 0.f, wr3 = 0.f, wi3 = 0.f;
#pragma unroll
        for (int jj = 0; jj < 32; jj += 4) {
            float2 u0 = us[buf][2 * jj + p];
            float2 u1 = us[buf][2 * (jj + 1) + p];
            float2 u2 = us[buf][2 * (jj + 2) + p];
            float2 u3 = us[buf][2 * (jj + 3) + p];
            wr0 = fmaf(Hr[jj],     u0.x, wr0); wr0 = fmaf(-Hi[jj],     u0.y, wr0);
            wi0 = fmaf(Hr[jj],     u0.y, wi0); wi0 = fmaf( Hi[jj],     u0.x, wi0);
            wr1 = fmaf(Hr[jj + 1], u1.x, wr1); wr1 = fmaf(-Hi[jj + 1], u1.y, wr1);
            wi1 = fmaf(Hr[jj + 1], u1.y, wi1); wi1 = fmaf( Hi[jj + 1], u1.x, wi1);
            wr2 = fmaf(Hr[jj + 2], u2.x, wr2); wr2 = fmaf(-Hi[jj + 2], u2.y, wr2);
            wi2 = fmaf(Hr[jj + 2], u2.y, wi2); wi2 = fmaf( Hi[jj + 2], u2.x, wi2);
            wr3 = fmaf(Hr[jj + 3], u3.x, wr3); wr3 = fmaf(-Hi[jj + 3], u3.y, wr3);
            wi3 = fmaf(Hr[jj + 3], u3.y, wi3); wi3 = fmaf( Hi[jj + 3], u3.x, wi3);
        }
        float wr = (wr0 + wr1) + (wr2 + wr3);
        float wi = (wi0 + wi1) + (wi2 + wi3);
        wr += __shfl_xor_sync(0xffffffffu, wr, 1);
        wi += __shfl_xor_sync(0xffffffffu, wi, 1);
        float tnr = fmaf(twoinva, wr, -tpr);
        float tni = fmaf(twoinva, wi, -tpi);
        tpr = tcr; tpi = tci; tcr = tnr; tci = tni;
        float g = 2.f * cf[k] * invn;
        int pp = k & 3;
        float gr = (pp == 0) ? g : ((pp == 2) ? -g : 0.f);
        float gi = (pp == 1) ? g : ((pp == 3) ? -g : 0.f);
        accr = fmaf(gr, tcr, accr); accr = fmaf(-gi, tci, accr);
        acci = fmaf(gr, tci, acci); acci = fmaf( gi, tcr, acci);
        buf ^= 1;
    }
    if (p == 0) { psr[r] = accr; psi_[r] = acci; }
    __syncthreads();

    // ---- observables -> qs[15] (threads 0..14) ----
    if (t < NOBS) {
        int a = PAIR_A[t], bw = PAIR_B[t];
        int pa = 5 - a, pb = 5 - bw;
        float dsum[4] = {0, 0, 0, 0};
        float orr[6] = {0, 0, 0, 0, 0, 0}, oii[6] = {0, 0, 0, 0, 0, 0};
        for (int rr_ = 0; rr_ < 16; rr_++) {
            int n0 = 0, rr = rr_;
#pragma unroll
            for (int pq = 0; pq < 6; pq++) {
                if (pq != pa && pq != pb) { n0 |= (rr & 1) << pq; rr >>= 1; }
            }
            float prk[4], pik[4];
#pragma unroll
            for (int k = 0; k < 4; k++) {
                int n = n0 | (((k >> 1) & 1) << pa) | ((k & 1) << pb);
                prk[k] = psr[n]; pik[k] = psi_[n];
            }
#pragma unroll
            for (int k = 0; k < 4; k++) dsum[k] += prk[k] * prk[k] + pik[k] * pik[k];
            int c = 0;
#pragma unroll
            for (int l = 1; l < 4; l++)
                for (int k = 0; k < l; k++) {
                    orr[c] += prk[k] * prk[l] + pik[k] * pik[l];
                    oii[c] += pik[k] * prk[l] - prk[k] * pik[l];
                    c++;
                }
        }
        float q = 0.f;
#pragma unroll
        for (int dd = 0; dd < 3; dd++) q += 2.f * Ddiag[t * 4 + dd + 1] * dsum[dd];
#pragma unroll
        for (int c = 0; c < 6; c++) {
            float A = Aoff[t * 6 + c], B = Boff[t * 6 + c];
            q += 2.f * (orr[c] * A - oii[c] * B);
        }
        qs[t] = q;
    }
    __syncthreads();

    // ---- fused head1: hh = silu(q @ Wv1 + bv1), 2 hidden cols per thread ----
    {
        int c0 = t * 2;
        float h0 = bv1[c0], h1 = bv1[c0 + 1];
#pragma unroll
        for (int j = 0; j < NOBS; j++) {
            float qv = qs[j];
            h0 = fmaf(qv, Wv1[j * HID + c0], h0);
            h1 = fmaf(qv, Wv1[j * HID + c0 + 1], h1);
        }
        float* o = g_hh + b * HID + c0;
        o[0] = h0 / (1.f + expf(-h0));
        o[1] = h1 / (1.f + expf(-h1));
    }
}

// ---------------- Kernel D: out = hh @ Wv2 + bv2 (f32x2, 8 rows x half-cols) ----------------
// grid (64, 2), 256 threads. Thread: col o = half*256+t, all 8 rows.
__global__ void k_head2(const float* __restrict__ Wv2, const float* __restrict__ bv2,
                        float* __restrict__ out) {
    __shared__ float hsT8[HID][8];   // 32B row stride, conflict-free fill
    int r0 = blockIdx.x * 8, t = threadIdx.x;
    int o  = blockIdx.y * 256 + t;
    for (int i = t; i < 8 * HID; i += 256) {
        int r = i & 7, j = i >> 3;
        hsT8[j][r] = g_hh[(r0 + r) * HID + j];
    }
    __syncthreads();
    ull acc[4];
#pragma unroll
    for (int p = 0; p < 4; p++) acc[p] = pk2(0.f, 0.f);
#pragma unroll 4
    for (int j = 0; j < HID; j++) {
        float w = Wv2[j * OUT_DIM + o];
        ull wd = pk2(w, w);
        longlong2 h0 = *(const longlong2*)&hsT8[j][0];   // rows 0..3 (broadcast)
        longlong2 h1 = *(const longlong2*)&hsT8[j][4];   // rows 4..7
        fma2(acc[0], (ull)h0.x, wd);
        fma2(acc[1], (ull)h0.y, wd);
        fma2(acc[2], (ull)h1.x, wd);
        fma2(acc[3], (ull)h1.y, wd);
    }
    float bo = bv2[o];
#pragma unroll
    for (int p = 0; p < 4; p++) {
        float2 v = up2(acc[p]);
        out[(r0 + 2 * p + 0) * OUT_DIM + o] = v.x + bo;
        out[(r0 + 2 * p + 1) * OUT_DIM + o] = v.y + bo;
    }
}

extern "C" void kernel_launch(void* const* d_in, const int* in_sizes, int n_in,
                              void* d_out, int out_size) {
    const float* x    = (const float*)d_in[0];
    const float* W1   = (const float*)d_in[1];
    const float* b1   = (const float*)d_in[2];
    const float* W2   = (const float*)d_in[3];
    const float* b2   = (const float*)d_in[4];
    const float* Aoff = (const float*)d_in[5];
    const float* Boff = (const float*)d_in[6];
    const float* Dd   = (const float*)d_in[7];
    const float* Wv1  = (const float*)d_in[8];
    const float* bv1  = (const float*)d_in[9];
    const float* Wv2  = (const float*)d_in[10];
    const float* bv2  = (const float*)d_in[11];
    // d_in[12] = pauli basis: unused (Pauli structure computed analytically)
    float* out = (float*)d_out;

    k_mlp1<<<BATCH / 8, 256>>>(x, W1, b1);
    dim3 g2(BATCH / 16, 4);
    k_mlp2<<<g2, 256>>>(W2, b2);
    k_expq<<<BATCH, 128>>>(Aoff, Boff, Dd, Wv1, bv1);
    dim3 gh(BATCH / 8, 2);
    k_head2<<<gh, 256>>>(Wv2, bv2, out);
}